// round 8
// baseline (speedup 1.0000x reference)
#include <cuda_runtime.h>

// Problem constants
#define NS 5
#define ND 64
#define NV 1024
#define NH 961
#define HPITCH 1092   // A copy: 63 zeros | 961 taps | 68 zeros (16B-aligned rows)
#define BPITCH 1088   // B copy: A shifted left by one float
#define NBAT 3        // batches per CTA
#define MAXB 4096

// Precomputed once per launch:
__device__ float g_hp[NS][HPITCH];   // zero-padded taps
__device__ float g_hb[NS][BPITCH];   // g_hb[i] = g_hp[i+1]
__device__ float g_sp[NS][NV];       // sp = conv_net(symbols), batch-independent
// Conv+silu output staging (written and re-read by the same CTA -> L2-hot)
__device__ float g_Y[MAXB * NS * NV];

__device__ __forceinline__ float silu_f(float y) {
    return y * (1.0f / (1.0f + __expf(-y)));
}

__device__ __forceinline__ float warp_sum(float v) {
#pragma unroll
    for (int o = 16; o; o >>= 1) v += __shfl_xor_sync(0xffffffffu, v, o);
    return v;
}

// packed dual-FMA: acc(lo,hi) += x(lo,hi) * g(lo,hi), elementwise fp32
__device__ __forceinline__ void ffma2(unsigned long long& acc,
                                      unsigned long long x,
                                      unsigned long long g) {
    asm("fma.rn.f32x2 %0, %1, %2, %0;" : "+l"(acc) : "l"(x), "l"(g));
}
__device__ __forceinline__ float u64lo(unsigned long long u) {
    return __uint_as_float((unsigned)u);
}
__device__ __forceinline__ float u64hi(unsigned long long u) {
    return __uint_as_float((unsigned)(u >> 32));
}

// ---- single-batch fully packed conv (used by sp_kernel only) ----
__device__ __forceinline__ void conv4p(const float* __restrict__ gA,
                                       const float* __restrict__ gB,
                                       const float* __restrict__ xs,
                                       float a[4]) {
    const ulonglong2* a2v = (const ulonglong2*)gA;
    const ulonglong2* b2v = (const ulonglong2*)gB;
    const ulonglong2* x2v = (const ulonglong2*)xs;
    unsigned long long A3 = 0ull, A2 = 0ull, A1 = 0ull, A0 = 0ull;
    ulonglong2 GA = a2v[0];
    ulonglong2 GB = b2v[0];
#pragma unroll
    for (int m = 0; m < 16; m++) {
        const ulonglong2 GAn = a2v[m + 1];
        const ulonglong2 GBn = b2v[m + 1];
        const ulonglong2 X = x2v[m];
        ffma2(A3, X.x, GA.x);
        ffma2(A1, X.x, GA.y);
        ffma2(A2, X.x, GB.x);
        ffma2(A0, X.x, GB.y);
        ffma2(A3, X.y, GA.y);
        ffma2(A1, X.y, GAn.x);
        ffma2(A2, X.y, GB.y);
        ffma2(A0, X.y, GBn.x);
        GA = GAn;
        GB = GBn;
    }
    a[3] = u64lo(A3) + u64hi(A3);
    a[2] = u64lo(A2) + u64hi(A2);
    a[1] = u64lo(A1) + u64hi(A1);
    a[0] = u64lo(A0) + u64hi(A0);
}

// --------------------------------------------------------------------------
// Kernel 1: pads h into g_hp + g_hb AND computes sp. 5 blocks, one per s.
// --------------------------------------------------------------------------
__global__ __launch_bounds__(256) void sp_kernel(
    const float* __restrict__ h, const float* __restrict__ symbols,
    const float* __restrict__ gamma, const float* __restrict__ beta) {
    __shared__ __align__(16) float hpA[HPITCH];
    __shared__ __align__(16) float hpB[BPITCH];
    __shared__ __align__(16) float xs[ND];
    __shared__ float wsum[8], wsq[8], mu_rs[2];
    const int s = blockIdx.x;
    const int t = threadIdx.x;
    const int warp = t >> 5, lane = t & 31;

    for (int i = t; i < HPITCH; i += 256) {
        const float v = (i >= 63 && i < 63 + NH) ? h[s * NH + (i - 63)] : 0.f;
        hpA[i] = v;
        g_hp[s][i] = v;
    }
    for (int i = t; i < BPITCH; i += 256) {
        const int j = i + 1;
        const float v = (j >= 63 && j < 63 + NH) ? h[s * NH + (j - 63)] : 0.f;
        hpB[i] = v;
        g_hb[s][i] = v;
    }
    if (t < ND) xs[t] = symbols[s * ND + t];
    __syncthreads();

    const int o0 = 4 * t;
    float a[4];
    conv4p(hpA + (1020 - o0), hpB + (1020 - o0), xs, a);

    float sm = 0.f, sq = 0.f;
#pragma unroll
    for (int k = 0; k < 4; k++) {
        a[k] = silu_f(a[k]);
        sm += a[k];
        sq += a[k] * a[k];
    }
    sm = warp_sum(sm);
    sq = warp_sum(sq);
    if (lane == 0) { wsum[warp] = sm; wsq[warp] = sq; }
    __syncthreads();
    if (t == 0) {
        float s1 = 0.f, s2 = 0.f;
#pragma unroll
        for (int w = 0; w < 8; w++) { s1 += wsum[w]; s2 += wsq[w]; }
        const float mu = s1 * (1.f / NV);
        mu_rs[0] = mu;
        mu_rs[1] = rsqrtf(s2 * (1.f / NV) - mu * mu + 1e-3f);
    }
    __syncthreads();
    const float mu = mu_rs[0], rstd = mu_rs[1];
#pragma unroll
    for (int k = 0; k < 4; k++) {
        const int o = o0 + k;
        g_sp[s][o] = (a[k] - mu) * rstd * gamma[o] + beta[o];
    }
}

// --------------------------------------------------------------------------
// Kernel 2: fused pipeline, THREE batches per CTA, 4 CTAs/SM.
// Window tap streams (2 LDS.128/m) are amortized over 3 batches; all MACs
// are packed f32x2. Silu'd conv output goes to a global scratch (L2-hot,
// same-CTA producer/consumer); LayerNorm is applied at epilogue read time.
// --------------------------------------------------------------------------
__global__ __launch_bounds__(256, 4) void main_kernel(
    const float* __restrict__ values,
    const float* __restrict__ gamma, const float* __restrict__ beta,
    float* __restrict__ out, int B) {
    __shared__ __align__(16) float hpA[NS][HPITCH];   // 21840 B
    __shared__ __align__(16) float hpB[NS][BPITCH];   // 21760 B
    __shared__ __align__(16) float xs[NBAT][NS][ND];  //  3840 B
    __shared__ float wsumF[NBAT][NS], wsqF[NBAT][NS]; //   120 B
    __shared__ float mu_s[NBAT][NS], rs_s[NBAT][NS];  //   120 B
    __shared__ int   spart[25][8];                    //   800 B
    __shared__ float prob[NS][NS];                    //   100 B

    const int b0 = NBAT * blockIdx.x;
    const int t = threadIdx.x;
    const int warp = t >> 5, lane = t & 31;
    const int o0 = 4 * t;

    if (t < 2 * NBAT * NS) (&wsumF[0][0])[t] = 0.f;   // wsumF then wsqF (adjacent)
    {   // taps + three batches' x (contiguous: b0..b0+2)
        const float4* srcA = (const float4*)(&g_hp[0][0]);
        float4* dstA = (float4*)(&hpA[0][0]);
        for (int i = t; i < NS * HPITCH / 4; i += 256) dstA[i] = srcA[i];
        const float4* srcB = (const float4*)(&g_hb[0][0]);
        float4* dstB = (float4*)(&hpB[0][0]);
        for (int i = t; i < NS * BPITCH / 4; i += 256) dstB[i] = srcB[i];
        const float4* v4 = (const float4*)(values + (size_t)b0 * (NS * ND));
        const int nbat = min(NBAT, B - b0);
        const int nfl = nbat * (NS * ND / 4);
        if (t < nfl) ((float4*)(&xs[0][0][0]))[t] = v4[t];
        else if (t < NBAT * NS * ND / 4)
            ((float4*)(&xs[0][0][0]))[t] = make_float4(0.f, 0.f, 0.f, 0.f);
    }
    __syncthreads();

    // ---- conv (batch-innermost) + silu -> g_Y, LN sums -> SMEM atomics ----
#pragma unroll
    for (int s = 0; s < NS; s++) {
        const ulonglong2* a2v = (const ulonglong2*)(&hpA[s][1020 - o0]);
        const ulonglong2* b2v = (const ulonglong2*)(&hpB[s][1020 - o0]);
        const ulonglong2* x0 = (const ulonglong2*)(&xs[0][s][0]);
        const ulonglong2* x1 = (const ulonglong2*)(&xs[1][s][0]);
        const ulonglong2* x2 = (const ulonglong2*)(&xs[2][s][0]);
        unsigned long long P3 = 0ull, P2 = 0ull, P1 = 0ull, P0 = 0ull;
        unsigned long long Q3 = 0ull, Q2 = 0ull, Q1 = 0ull, Q0 = 0ull;
        unsigned long long R3 = 0ull, R2 = 0ull, R1 = 0ull, R0 = 0ull;
        ulonglong2 GA = a2v[0];
        ulonglong2 GB = b2v[0];
#pragma unroll
        for (int m = 0; m < 16; m++) {
            const ulonglong2 GAn = a2v[m + 1];
            const ulonglong2 GBn = b2v[m + 1];
            const ulonglong2 X = x0[m];
            const ulonglong2 Y = x1[m];
            const ulonglong2 Z = x2[m];
            ffma2(P3, X.x, GA.x);  ffma2(P1, X.x, GA.y);
            ffma2(P2, X.x, GB.x);  ffma2(P0, X.x, GB.y);
            ffma2(P3, X.y, GA.y);  ffma2(P1, X.y, GAn.x);
            ffma2(P2, X.y, GB.y);  ffma2(P0, X.y, GBn.x);
            ffma2(Q3, Y.x, GA.x);  ffma2(Q1, Y.x, GA.y);
            ffma2(Q2, Y.x, GB.x);  ffma2(Q0, Y.x, GB.y);
            ffma2(Q3, Y.y, GA.y);  ffma2(Q1, Y.y, GAn.x);
            ffma2(Q2, Y.y, GB.y);  ffma2(Q0, Y.y, GBn.x);
            ffma2(R3, Z.x, GA.x);  ffma2(R1, Z.x, GA.y);
            ffma2(R2, Z.x, GB.x);  ffma2(R0, Z.x, GB.y);
            ffma2(R3, Z.y, GA.y);  ffma2(R1, Z.y, GAn.x);
            ffma2(R2, Z.y, GB.y);  ffma2(R0, Z.y, GBn.x);
            GA = GAn;
            GB = GBn;
        }
#pragma unroll
        for (int bb = 0; bb < NBAT; bb++) {
            float a[4];
            if (bb == 0) {
                a[3] = u64lo(P3) + u64hi(P3); a[2] = u64lo(P2) + u64hi(P2);
                a[1] = u64lo(P1) + u64hi(P1); a[0] = u64lo(P0) + u64hi(P0);
            } else if (bb == 1) {
                a[3] = u64lo(Q3) + u64hi(Q3); a[2] = u64lo(Q2) + u64hi(Q2);
                a[1] = u64lo(Q1) + u64hi(Q1); a[0] = u64lo(Q0) + u64hi(Q0);
            } else {
                a[3] = u64lo(R3) + u64hi(R3); a[2] = u64lo(R2) + u64hi(R2);
                a[1] = u64lo(R1) + u64hi(R1); a[0] = u64lo(R0) + u64hi(R0);
            }
            float sm = 0.f, sq = 0.f;
#pragma unroll
            for (int k = 0; k < 4; k++) {
                a[k] = silu_f(a[k]);
                sm += a[k]; sq += a[k] * a[k];
            }
            sm = warp_sum(sm);
            sq = warp_sum(sq);
            if (lane == 0) {
                atomicAdd(&wsumF[bb][s], sm);
                atomicAdd(&wsqF[bb][s], sq);
            }
            if (b0 + bb < B) {
                float4* y4 = (float4*)(g_Y + ((size_t)(b0 + bb) * NS + s) * NV);
                y4[t] = make_float4(a[0], a[1], a[2], a[3]);
            }
        }
    }
    __syncthreads();
    if (t < NBAT * NS) {
        const int bb = t / NS, ss = t % NS;
        const float mu = wsumF[bb][ss] * (1.f / NV);
        mu_s[bb][ss] = mu;
        rs_s[bb][ss] = rsqrtf(wsqF[bb][ss] * (1.f / NV) - mu * mu + 1e-3f);
    }
    __syncthreads();

    // ---- epilogue, per batch sequentially; LN applied at read time ----
    const float4 gm4 = ((const float4*)gamma)[t];
    const float4 bt4 = ((const float4*)beta)[t];
    float4 SP[NS];
#pragma unroll
    for (int j = 0; j < NS; j++) SP[j] = ((const float4*)(&g_sp[j][0]))[t];

#pragma unroll
    for (int bb = 0; bb < NBAT; bb++) {
        if (b0 + bb >= B) break;

        float4 VPX[NS];
#pragma unroll
        for (int i = 0; i < NS; i++) {
            const float4 v = ((const float4*)(g_Y + ((size_t)(b0 + bb) * NS + i) * NV))[t];
            const float mu = mu_s[bb][i], rs = rs_s[bb][i];
            VPX[i].x = (v.x - mu) * rs * gm4.x + bt4.x;
            VPX[i].y = (v.y - mu) * rs * gm4.y + bt4.y;
            VPX[i].z = (v.z - mu) * rs * gm4.z + bt4.z;
            VPX[i].w = (v.w - mu) * rs * gm4.w + bt4.w;
        }

        // scores: sign(v)*sign(v+sp) = 1 - 2*(signbit xor); count flips.
#pragma unroll
        for (int j = 0; j < NS; j++) {
            const float spv[4] = {SP[j].x, SP[j].y, SP[j].z, SP[j].w};
#pragma unroll
            for (int i = 0; i < NS; i++) {
                const float vv[4] = {VPX[i].x, VPX[i].y, VPX[i].z, VPX[i].w};
                int a = 0;
#pragma unroll
                for (int k = 0; k < 4; k++) {
                    const float c = vv[k] + spv[k];
                    a += (int)((__float_as_uint(vv[k]) ^
                                __float_as_uint(c)) >> 31);
                }
                const int v = __reduce_add_sync(0xffffffffu, a);
                if (lane == 0) spart[j * NS + i][warp] = v;
            }
        }
        __syncthreads();
        if (t < 25) {
            int sm = 0;
#pragma unroll
            for (int w = 0; w < 8; w++) sm += spart[t][w];
            ((float*)&spart[t][0])[0] = (float)(NV - 2 * sm) * (1.f / NV);
        }
        __syncthreads();
        if (t < NS) {
            float sc[NS], m = -1e30f;
#pragma unroll
            for (int i = 0; i < NS; i++) {
                sc[i] = ((float*)&spart[t * NS + i][0])[0];
                m = fmaxf(m, sc[i]);
            }
            float ssum = 0.f;
#pragma unroll
            for (int i = 0; i < NS; i++) { sc[i] = __expf(sc[i] - m); ssum += sc[i]; }
            const float inv = 1.f / ssum;
#pragma unroll
            for (int i = 0; i < NS; i++) prob[t][i] = sc[i] * inv;
        }
        __syncthreads();

        float4* out4 = (float4*)(out + (size_t)(b0 + bb) * (NS * NV));
#pragma unroll
        for (int j = 0; j < NS; j++) {
            const float p0 = prob[j][0], p1 = prob[j][1], p2 = prob[j][2],
                        p3 = prob[j][3], p4 = prob[j][4];
            const float spv[4] = {SP[j].x, SP[j].y, SP[j].z, SP[j].w};
            float r[4];
#pragma unroll
            for (int k = 0; k < 4; k++) {
                const float v0 = ((const float*)&VPX[0])[k];
                const float v1 = ((const float*)&VPX[1])[k];
                const float v2 = ((const float*)&VPX[2])[k];
                const float v3 = ((const float*)&VPX[3])[k];
                const float v4 = ((const float*)&VPX[4])[k];
                const float atv = p0 * v0 + p1 * v1 + p2 * v2 + p3 * v3 + p4 * v4;
                r[k] = silu_f(atv * spv[k]);
            }
            float4 w4;
            w4.x = r[0]; w4.y = r[1]; w4.z = r[2]; w4.w = r[3];
            out4[j * 256 + t] = w4;
        }
        __syncthreads();   // protect spart/prob before next batch
    }
}

extern "C" void kernel_launch(void* const* d_in, const int* in_sizes, int n_in,
                              void* d_out, int out_size) {
    const float* values  = (const float*)d_in[0];
    const float* h       = (const float*)d_in[1];
    const float* symbols = (const float*)d_in[2];
    const float* gamma   = (const float*)d_in[3];
    const float* beta    = (const float*)d_in[4];
    float* out = (float*)d_out;

    const int B = in_sizes[0] / (NS * ND);

    sp_kernel<<<NS, 256>>>(h, symbols, gamma, beta);
    main_kernel<<<(B + NBAT - 1) / NBAT, 256>>>(values, gamma, beta, out, B);
}